// round 14
// baseline (speedup 1.0000x reference)
#include <cuda_runtime.h>
#include <cuda_bf16.h>
#include <math.h>
#include <stdint.h>

// Problem constants
constexpr int S_ = 256;
constexpr int Bb = 32;
constexpr int Hh = 512;
constexpr int Pp = 2048;
constexpr int Tt = Pp + S_;     // 2304
constexpr int Mm = Bb * S_;     // 8192
constexpr int Ff = 4 * Hh;      // 2048
constexpr int QKVN = 3 * Hh;    // 1536

constexpr float SCALE = 0.044194173824159223f;  // 1/sqrt(512)

// Scratch
__device__ float g_qkv[(size_t)Mm * QKVN];
__device__ float g_sc[(size_t)Mm * Tt];            // unnormalized probs (p~)
__device__ float g_rp[(size_t)Bb * 4 * 36 * 64];   // row partial sums
__device__ float g_at[(size_t)Mm * Hh];
__device__ float g_h1[(size_t)Mm * Hh];            // exact (residual)
__device__ float g_h1r[(size_t)Mm * Hh];           // rounded (FFN-A)
__device__ float g_act[(size_t)Mm * Ff];
// Pre-rounded inputs
__device__ float g_hr[(size_t)Mm * Hh];
__device__ float g_wqkv[Hh * QKVN];
__device__ float g_bqkv[QKVN];
__device__ float g_wo[Hh * Hh];
__device__ float g_w1[Hh * Ff];
__device__ float g_w2[Ff * Hh];

__device__ __forceinline__ size_t hid_off(int m) {
    int b = m >> 8;
    int s = m & (S_ - 1);
    return ((size_t)s * Bb + b) * Hh;
}

__device__ __forceinline__ float rnd_tf32(float x) {
    uint32_t u;
    asm("cvt.rna.tf32.f32 %0, %1;" : "=r"(u) : "f"(x));
    return __uint_as_float(u);
}

__device__ __forceinline__ void mma8(float* d, const uint32_t* a, const uint32_t* b) {
    asm volatile(
        "mma.sync.aligned.m16n8k8.row.col.f32.tf32.tf32.f32 "
        "{%0,%1,%2,%3},{%4,%5,%6,%7},{%8,%9},{%0,%1,%2,%3};"
        : "+f"(d[0]), "+f"(d[1]), "+f"(d[2]), "+f"(d[3])
        : "r"(a[0]), "r"(a[1]), "r"(a[2]), "r"(a[3]), "r"(b[0]), "r"(b[1]));
}

__device__ __forceinline__ void cp16(void* smem, const void* g) {
    uint32_t s = (uint32_t)__cvta_generic_to_shared(smem);
    asm volatile("cp.async.cg.shared.global [%0], [%1], 16;" :: "r"(s), "l"(g));
}
__device__ __forceinline__ void cp_commit() { asm volatile("cp.async.commit_group;"); }
template<int N>
__device__ __forceinline__ void cp_wait() { asm volatile("cp.async.wait_group %0;" :: "n"(N)); }

__device__ __forceinline__ uint32_t u32of(float f) { return __float_as_uint(f); }

#define BM 64
#define BN 128
#define BK 16
#define AKP 20
#define BNP 136
#define STG 4      // pipeline stages: dense GEMMs + PV
#define STS 3      // pipeline stages: scores
#define NT 128
#define OCC 4

enum { E_BIAS = 0, E_GELU = 1, E_RES_HID = 2, E_RES_TRANS = 3 };

constexpr int SMEM_GEMM   = STG * (BM * AKP + BK * BNP) * 4;   // 55296
constexpr int SMEM_SCORES = STS * (BM * AKP + BN * AKP) * 4;   // 46080

// ---------------------------------------------------------------------------
// Prep: round to tf32 (RNA), pack QKV weights+bias.
// ---------------------------------------------------------------------------
constexpr int F4_HR   = Mm * Hh / 4;
constexpr int F4_WO   = Hh * Hh / 4;
constexpr int F4_W1   = Hh * Ff / 4;
constexpr int F4_W2   = Ff * Hh / 4;
constexpr int F4_WQKV = Hh * QKVN / 4;
constexpr int F4_BQKV = QKVN / 4;
constexpr int F4_TOTAL = F4_HR + F4_WO + F4_W1 + F4_W2 + F4_WQKV + F4_BQKV;

__global__ __launch_bounds__(256)
void prep_kernel(const float* __restrict__ hidden,
                 const float* __restrict__ Wq, const float* __restrict__ Wk,
                 const float* __restrict__ Wv, const float* __restrict__ Wo,
                 const float* __restrict__ W1, const float* __restrict__ W2,
                 const float* __restrict__ bq, const float* __restrict__ bk,
                 const float* __restrict__ bv)
{
    int i = blockIdx.x * blockDim.x + threadIdx.x;
    if (i >= F4_TOTAL) return;

    auto rc = [](const float* s, float* d, int idx) {
        float4 v = reinterpret_cast<const float4*>(s)[idx];
        v.x = rnd_tf32(v.x); v.y = rnd_tf32(v.y);
        v.z = rnd_tf32(v.z); v.w = rnd_tf32(v.w);
        reinterpret_cast<float4*>(d)[idx] = v;
    };

    if (i < F4_HR) { rc(hidden, g_hr, i); return; }
    i -= F4_HR;
    if (i < F4_WO) { rc(Wo, g_wo, i); return; }
    i -= F4_WO;
    if (i < F4_W1) { rc(W1, g_w1, i); return; }
    i -= F4_W1;
    if (i < F4_W2) { rc(W2, g_w2, i); return; }
    i -= F4_W2;
    if (i < F4_WQKV) {
        int row = i / (QKVN / 4);
        int j4  = i % (QKVN / 4);
        int sel = j4 >> 7;
        int col4 = j4 & 127;
        const float* src = (sel == 0) ? Wq : (sel == 1) ? Wk : Wv;
        float4 v = reinterpret_cast<const float4*>(src + (size_t)row * Hh)[col4];
        v.x = rnd_tf32(v.x); v.y = rnd_tf32(v.y);
        v.z = rnd_tf32(v.z); v.w = rnd_tf32(v.w);
        reinterpret_cast<float4*>(g_wqkv + (size_t)row * QKVN)[j4] = v;
        return;
    }
    i -= F4_WQKV;
    {
        int sel = i >> 7;
        int col4 = i & 127;
        const float* src = (sel == 0) ? bq : (sel == 1) ? bk : bv;
        reinterpret_cast<float4*>(g_bqkv)[i] = reinterpret_cast<const float4*>(src)[col4];
    }
}

// ---------------------------------------------------------------------------
// 32x64 warp-tile mainloop core (4 warps => 64x128 CTA tile).
// ---------------------------------------------------------------------------
struct Frag {
    float acc[2][8][4];
    __device__ __forceinline__ void zero() {
        #pragma unroll
        for (int i = 0; i < 2; i++)
            #pragma unroll
            for (int j = 0; j < 8; j++)
                #pragma unroll
                for (int t = 0; t < 4; t++) acc[i][j][t] = 0.f;
    }
};

template<bool BKN>
__device__ __forceinline__ void tile_mma(Frag& F, const float* Ab, const float* Bbuf,
                                         int wm, int wn, int lr, int lc)
{
    #pragma unroll
    for (int ks = 0; ks < 2; ks++) {
        const int kk = ks * 8 + lc;
        uint32_t af[2][4];
        #pragma unroll
        for (int mt = 0; mt < 2; mt++) {
            int r = wm * 32 + mt * 16 + lr;
            af[mt][0] = u32of(Ab[r * AKP + kk]);
            af[mt][1] = u32of(Ab[(r + 8) * AKP + kk]);
            af[mt][2] = u32of(Ab[r * AKP + kk + 4]);
            af[mt][3] = u32of(Ab[(r + 8) * AKP + kk + 4]);
        }
        uint32_t bf[8][2];
        #pragma unroll
        for (int nt = 0; nt < 8; nt++) {
            int cc = wn * 64 + nt * 8 + lr;
            if (BKN) {
                bf[nt][0] = u32of(Bbuf[kk * BNP + cc]);
                bf[nt][1] = u32of(Bbuf[(kk + 4) * BNP + cc]);
            } else {
                bf[nt][0] = u32of(Bbuf[cc * AKP + kk]);
                bf[nt][1] = u32of(Bbuf[cc * AKP + kk + 4]);
            }
        }
        #pragma unroll
        for (int mt = 0; mt < 2; mt++)
            #pragma unroll
            for (int nt = 0; nt < 8; nt++)
                mma8(F.acc[mt][nt], af[mt], bf[nt]);
    }
}

// ---------------------------------------------------------------------------
// Standard GEMM (STG stages)
// ---------------------------------------------------------------------------
template<bool AHID, int EPI, bool ROUND>
__global__ __launch_bounds__(NT, OCC)
void gemm_tc(const float* __restrict__ A, const float* __restrict__ W,
             const float* __restrict__ bias, const float* __restrict__ R,
             float* __restrict__ C, float* __restrict__ C2, int K, int N, int CN)
{
    extern __shared__ float sm[];
    float* As = sm;
    float* Bs = sm + STG * BM * AKP;

    const int tid  = threadIdx.x;
    const int lane = tid & 31;
    const int warp = tid >> 5;
    const int wm   = warp & 1;
    const int wn   = warp >> 1;
    const int lr   = lane >> 2;
    const int lc   = lane & 3;
    const int m0   = blockIdx.y * BM;
    const int n0   = blockIdx.x * BN;
    const int KT   = K / BK;

    auto issue = [&](int kt) {
        int st = kt % STG;
        float* Ad = As + st * BM * AKP;
        float* Bd = Bs + st * BK * BNP;
        #pragma unroll
        for (int u = 0; u < 2; u++) {
            int c = tid + u * NT;
            int m = c >> 2, k4 = c & 3;
            const float* g = (AHID ? (A + hid_off(m0 + m)) : (A + (size_t)(m0 + m) * K))
                             + kt * BK + k4 * 4;
            cp16(Ad + m * AKP + k4 * 4, g);
        }
        #pragma unroll
        for (int u = 0; u < 4; u++) {
            int c = tid + u * NT;
            int k = c >> 5, n4 = c & 31;
            cp16(Bd + k * BNP + n4 * 4, W + (size_t)(kt * BK + k) * N + n0 + n4 * 4);
        }
        cp_commit();
    };

    Frag F; F.zero();

    #pragma unroll
    for (int p = 0; p < STG - 1; p++) issue(p);

    for (int kt = 0; kt < KT; ++kt) {
        cp_wait<STG - 2>();
        __syncthreads();
        tile_mma<true>(F, As + (kt % STG) * BM * AKP, Bs + (kt % STG) * BK * BNP,
                       wm, wn, lr, lc);
        if (kt + STG - 1 < KT) issue(kt + STG - 1); else cp_commit();
    }

    #pragma unroll
    for (int nt = 0; nt < 8; nt++) {
        int c = n0 + wn * 64 + nt * 8 + lc * 2;
        float bv0 = bias[c], bv1 = bias[c + 1];
        #pragma unroll
        for (int mt = 0; mt < 2; mt++) {
            int r0 = m0 + wm * 32 + mt * 16 + lr;
            int r1 = r0 + 8;
            float v00 = F.acc[mt][nt][0] + bv0;
            float v01 = F.acc[mt][nt][1] + bv1;
            float v10 = F.acc[mt][nt][2] + bv0;
            float v11 = F.acc[mt][nt][3] + bv1;
            if (EPI == E_GELU) {
                v00 = 0.5f * v00 * (1.f + erff(v00 * 0.70710678118654752f));
                v01 = 0.5f * v01 * (1.f + erff(v01 * 0.70710678118654752f));
                v10 = 0.5f * v10 * (1.f + erff(v10 * 0.70710678118654752f));
                v11 = 0.5f * v11 * (1.f + erff(v11 * 0.70710678118654752f));
            } else if (EPI == E_RES_HID) {
                const float* rp0 = R + hid_off(r0) + c;
                const float* rp1 = R + hid_off(r1) + c;
                v00 += rp0[0]; v01 += rp0[1];
                v10 += rp1[0]; v11 += rp1[1];
            } else if (EPI == E_RES_TRANS) {
                const float* rp0 = R + (size_t)r0 * CN + c;
                const float* rp1 = R + (size_t)r1 * CN + c;
                v00 += rp0[0]; v01 += rp0[1];
                v10 += rp1[0]; v11 += rp1[1];
            }
            if (EPI == E_RES_HID) {
                *reinterpret_cast<float2*>(C  + (size_t)r0 * CN + c) = make_float2(v00, v01);
                *reinterpret_cast<float2*>(C  + (size_t)r1 * CN + c) = make_float2(v10, v11);
                *reinterpret_cast<float2*>(C2 + (size_t)r0 * CN + c) =
                    make_float2(rnd_tf32(v00), rnd_tf32(v01));
                *reinterpret_cast<float2*>(C2 + (size_t)r1 * CN + c) =
                    make_float2(rnd_tf32(v10), rnd_tf32(v11));
            } else {
                if (ROUND) {
                    v00 = rnd_tf32(v00); v01 = rnd_tf32(v01);
                    v10 = rnd_tf32(v10); v11 = rnd_tf32(v11);
                }
                if (EPI == E_RES_TRANS) {
                    *reinterpret_cast<float2*>(C + hid_off(r0) + c) = make_float2(v00, v01);
                    *reinterpret_cast<float2*>(C + hid_off(r1) + c) = make_float2(v10, v11);
                } else {
                    *reinterpret_cast<float2*>(C + (size_t)r0 * CN + c) = make_float2(v00, v01);
                    *reinterpret_cast<float2*>(C + (size_t)r1 * CN + c) = make_float2(v10, v11);
                }
            }
        }
    }
}

// ---------------------------------------------------------------------------
// Scores (STS stages): b = blockIdx.x (fastest) so heavy/dead batches spread
// across SMs. m = blockIdx.y, n-tile = blockIdx.z.
// g_rp layout: [b][mtile(4)][slot(36 = ntile*2 + wn)][row(64)]
// ---------------------------------------------------------------------------
__global__ __launch_bounds__(NT, OCC)
void scores_tc(const float* __restrict__ qkv, const float* __restrict__ past_k,
               const int* __restrict__ past_lens, float* __restrict__ scores,
               float* __restrict__ rpart)
{
    extern __shared__ float sm[];
    float* As = sm;
    float* Bs = sm + STS * BM * AKP;

    const int tid  = threadIdx.x;
    const int lane = tid & 31;
    const int warp = tid >> 5;
    const int wm   = warp & 1;
    const int wn   = warp >> 1;
    const int lr   = lane >> 2;
    const int lc   = lane & 3;
    const int b    = blockIdx.x;
    const int m0   = blockIdx.y * BM;
    const int n0   = blockIdx.z * BN;
    const int KT   = Hh / BK;

    const int L = past_lens[b];
    float* rpb = rpart + ((size_t)(b * 4 + (m0 >> 6)) * 36 + (n0 >> 7) * 2) * 64;

    bool dead = (n0 + BN <= Pp) ? (n0 >= L)
              : ((n0 >= Pp) && (n0 - Pp) > m0 + BM - 1);
    if (dead) {
        #pragma unroll
        for (int mt = 0; mt < 2; mt++)
            #pragma unroll
            for (int nt = 0; nt < 8; nt++) {
                int c = n0 + wn * 64 + nt * 8 + lc * 2;
                #pragma unroll
                for (int half = 0; half < 2; half++) {
                    int s = m0 + wm * 32 + mt * 16 + lr + half * 8;
                    *reinterpret_cast<float2*>(scores + ((size_t)b * S_ + s) * Tt + c) =
                        make_float2(0.f, 0.f);
                }
            }
        rpb[tid] = 0.f;
        return;
    }

    const float* Aq = qkv + (size_t)b * S_ * QKVN;

    auto keyrow = [&](int j) -> const float* {
        return (j < Pp) ? (past_k + ((size_t)b * Pp + j) * Hh)
                        : (qkv + ((size_t)b * S_ + (j - Pp)) * QKVN + Hh);
    };
    auto issue = [&](int kt) {
        int st = kt % STS;
        float* Ad = As + st * BM * AKP;
        float* Bd = Bs + st * BN * AKP;
        #pragma unroll
        for (int u = 0; u < 2; u++) {
            int c = tid + u * NT;
            int m = c >> 2, k4 = c & 3;
            cp16(Ad + m * AKP + k4 * 4, Aq + (size_t)(m0 + m) * QKVN + kt * BK + k4 * 4);
        }
        #pragma unroll
        for (int u = 0; u < 4; u++) {
            int c = tid + u * NT;
            int n = c >> 2, k4 = c & 3;
            cp16(Bd + n * AKP + k4 * 4, keyrow(n0 + n) + kt * BK + k4 * 4);
        }
        cp_commit();
    };

    Frag F; F.zero();

    #pragma unroll
    for (int p = 0; p < STS - 1; p++) issue(p);

    for (int kt = 0; kt < KT; ++kt) {
        cp_wait<STS - 2>();
        __syncthreads();
        tile_mma<false>(F, As + (kt % STS) * BM * AKP, Bs + (kt % STS) * BN * AKP,
                        wm, wn, lr, lc);
        if (kt + STS - 1 < KT) issue(kt + STS - 1); else cp_commit();
    }

    float rsum[4];
    #pragma unroll
    for (int i = 0; i < 4; i++) rsum[i] = 0.f;

    #pragma unroll
    for (int mt = 0; mt < 2; mt++)
        #pragma unroll
        for (int nt = 0; nt < 8; nt++) {
            int c = n0 + wn * 64 + nt * 8 + lc * 2;
            #pragma unroll
            for (int half = 0; half < 2; half++) {
                int s = m0 + wm * 32 + mt * 16 + lr + half * 8;
                float v0 = F.acc[mt][nt][half * 2 + 0];
                float v1 = F.acc[mt][nt][half * 2 + 1];
                bool ok0 = (c < Pp) ? (c < L) : ((c - Pp) <= s);
                int c1 = c + 1;
                bool ok1 = (c1 < Pp) ? (c1 < L) : ((c1 - Pp) <= s);
                float e0 = ok0 ? rnd_tf32(__expf(v0 * SCALE)) : 0.f;
                float e1 = ok1 ? rnd_tf32(__expf(v1 * SCALE)) : 0.f;
                rsum[mt * 2 + half] += e0 + e1;
                *reinterpret_cast<float2*>(scores + ((size_t)b * S_ + s) * Tt + c) =
                    make_float2(e0, e1);
            }
        }

    #pragma unroll
    for (int i = 0; i < 4; i++) {
        float v = rsum[i];
        v += __shfl_xor_sync(0xffffffffu, v, 1);
        v += __shfl_xor_sync(0xffffffffu, v, 2);
        rsum[i] = v;
    }
    if (lc == 0) {
        #pragma unroll
        for (int mt = 0; mt < 2; mt++)
            #pragma unroll
            for (int half = 0; half < 2; half++) {
                int rowl = wm * 32 + mt * 16 + lr + half * 8;
                rpb[wn * 64 + rowl] = rsum[mt * 2 + half];
            }
    }
}

// ---------------------------------------------------------------------------
// PV (STG stages): b = blockIdx.x (fastest) to spread variable-length work.
// ---------------------------------------------------------------------------
__global__ __launch_bounds__(NT, OCC)
void pv_tc(const float* __restrict__ probs, const float* __restrict__ past_v,
           const float* __restrict__ qkv, float* __restrict__ attn,
           const int* __restrict__ past_lens, const float* __restrict__ rpart)
{
    extern __shared__ float sm[];
    float* As = sm;
    float* Bs = sm + STG * BM * AKP;
    __shared__ float sinv[BM];

    const int tid  = threadIdx.x;
    const int lane = tid & 31;
    const int warp = tid >> 5;
    const int wm   = warp & 1;
    const int wn   = warp >> 1;
    const int lr   = lane >> 2;
    const int lc   = lane & 3;
    const int b    = blockIdx.x;
    const int m0   = blockIdx.y * BM;
    const int n0   = blockIdx.z * BN;

    if (tid < BM) {
        const float* rp = rpart + (size_t)(b * 4 + (m0 >> 6)) * 36 * 64 + tid;
        float s = 0.f;
        #pragma unroll
        for (int t = 0; t < 36; t++) s += rp[t * 64];
        sinv[tid] = 1.f / s;
    }

    const int L  = past_lens[b];
    const int ne = (L + 15) >> 4;
    const int nn = (m0 >> 4) + 4;
    const int total = ne + nn;

    const float* Ap = probs + (size_t)b * S_ * Tt;

    auto kmap = [&](int i) { return (i < ne) ? i : 128 + (i - ne); };
    auto vrow = [&](int kidx) -> const float* {
        return (kidx < Pp) ? (past_v + ((size_t)b * Pp + kidx) * Hh)
                           : (qkv + ((size_t)b * S_ + (kidx - Pp)) * QKVN + 2 * Hh);
    };
    auto issue = [&](int i) {
        int kt = kmap(i);
        int st = i % STG;
        float* Ad = As + st * BM * AKP;
        float* Bd = Bs + st * BK * BNP;
        #pragma unroll
        for (int u = 0; u < 2; u++) {
            int c = tid + u * NT;
            int m = c >> 2, k4 = c & 3;
            cp16(Ad + m * AKP + k4 * 4, Ap + (size_t)(m0 + m) * Tt + kt * BK + k4 * 4);
        }
        #pragma unroll
        for (int u = 0; u < 4; u++) {
            int c = tid + u * NT;
            int k = c >> 5, n4 = c & 31;
            cp16(Bd + k * BNP + n4 * 4, vrow(kt * BK + k) + n0 + n4 * 4);
        }
        cp_commit();
    };

    Frag F; F.zero();

    #pragma unroll
    for (int p = 0; p < STG - 1; p++) if (p < total) issue(p);

    for (int i = 0; i < total; ++i) {
        cp_wait<STG - 2>();
        __syncthreads();
        tile_mma<true>(F, As + (i % STG) * BM * AKP, Bs + (i % STG) * BK * BNP,
                       wm, wn, lr, lc);
        if (i + STG - 1 < total) issue(i + STG - 1); else cp_commit();
    }
    __syncthreads();

    #pragma unroll
    for (int mt = 0; mt < 2; mt++)
        #pragma unroll
        for (int nt = 0; nt < 8; nt++) {
            int c = n0 + wn * 64 + nt * 8 + lc * 2;
            int rl0 = wm * 32 + mt * 16 + lr;
            int rl1 = rl0 + 8;
            int r0 = m0 + rl0;
            int r1 = m0 + rl1;
            float i0 = sinv[rl0], i1 = sinv[rl1];
            *reinterpret_cast<float2*>(attn + ((size_t)b * S_ + r0) * Hh + c) =
                make_float2(rnd_tf32(F.acc[mt][nt][0] * i0), rnd_tf32(F.acc[mt][nt][1] * i0));
            *reinterpret_cast<float2*>(attn + ((size_t)b * S_ + r1) * Hh + c) =
                make_float2(rnd_tf32(F.acc[mt][nt][2] * i1), rnd_tf32(F.acc[mt][nt][3] * i1));
        }
}

// ---------------------------------------------------------------------------
// Launch
// ---------------------------------------------------------------------------
extern "C" void kernel_launch(void* const* d_in, const int* in_sizes, int n_in,
                              void* d_out, int out_size)
{
    const float* hidden    = (const float*)d_in[0];
    const float* past_k    = (const float*)d_in[1];
    const float* past_v    = (const float*)d_in[2];
    const int*   past_lens = (const int*)  d_in[3];
    const float* Wq = (const float*)d_in[4];  const float* bq = (const float*)d_in[5];
    const float* Wk = (const float*)d_in[6];  const float* bk = (const float*)d_in[7];
    const float* Wv = (const float*)d_in[8];  const float* bv = (const float*)d_in[9];
    const float* Wo = (const float*)d_in[10]; const float* bo = (const float*)d_in[11];
    const float* W1 = (const float*)d_in[12]; const float* b1 = (const float*)d_in[13];
    const float* W2 = (const float*)d_in[14]; const float* b2 = (const float*)d_in[15];
    float* out = (float*)d_out;

    float *qkv, *sc, *rp, *at, *h1, *h1r, *act, *hr, *wqkv, *bqkv, *wo, *w1, *w2;
    cudaGetSymbolAddress((void**)&qkv,  g_qkv);
    cudaGetSymbolAddress((void**)&sc,   g_sc);
    cudaGetSymbolAddress((void**)&rp,   g_rp);
    cudaGetSymbolAddress((void**)&at,   g_at);
    cudaGetSymbolAddress((void**)&h1,   g_h1);
    cudaGetSymbolAddress((void**)&h1r,  g_h1r);
    cudaGetSymbolAddress((void**)&act,  g_act);
    cudaGetSymbolAddress((void**)&hr,   g_hr);
    cudaGetSymbolAddress((void**)&wqkv, g_wqkv);
    cudaGetSymbolAddress((void**)&bqkv, g_bqkv);
    cudaGetSymbolAddress((void**)&wo,   g_wo);
    cudaGetSymbolAddress((void**)&w1,   g_w1);
    cudaGetSymbolAddress((void**)&w2,   g_w2);

    cudaFuncSetAttribute(gemm_tc<true,  E_BIAS,      true >, cudaFuncAttributeMaxDynamicSharedMemorySize, SMEM_GEMM);
    cudaFuncSetAttribute(gemm_tc<false, E_RES_HID,   false>, cudaFuncAttributeMaxDynamicSharedMemorySize, SMEM_GEMM);
    cudaFuncSetAttribute(gemm_tc<false, E_GELU,      true >, cudaFuncAttributeMaxDynamicSharedMemorySize, SMEM_GEMM);
    cudaFuncSetAttribute(gemm_tc<false, E_RES_TRANS, false>, cudaFuncAttributeMaxDynamicSharedMemorySize, SMEM_GEMM);
    cudaFuncSetAttribute(scores_tc, cudaFuncAttributeMaxDynamicSharedMemorySize, SMEM_SCORES);
    cudaFuncSetAttribute(pv_tc,     cudaFuncAttributeMaxDynamicSharedMemorySize, SMEM_GEMM);

    prep_kernel<<<(F4_TOTAL + 255) / 256, 256>>>(hidden, Wq, Wk, Wv, Wo, W1, W2, bq, bk, bv);

    dim3 blk(NT);

    gemm_tc<true, E_BIAS, true><<<dim3(QKVN / BN, Mm / BM), blk, SMEM_GEMM>>>(
        hr, wqkv, bqkv, nullptr, qkv, nullptr, Hh, QKVN, QKVN);

    // b fastest-varying: spreads variable-work batches across SMs
    scores_tc<<<dim3(Bb, S_ / BM, Tt / BN), blk, SMEM_SCORES>>>(qkv, past_k, past_lens, sc, rp);
    pv_tc<<<dim3(Bb, S_ / BM, Hh / BN), blk, SMEM_GEMM>>>(sc, past_v, qkv, at, past_lens, rp);

    gemm_tc<false, E_RES_HID, false><<<dim3(Hh / BN, Mm / BM), blk, SMEM_GEMM>>>(
        at, wo, bo, hidden, h1, h1r, Hh, Hh, Hh);

    gemm_tc<false, E_GELU, true><<<dim3(Ff / BN, Mm / BM), blk, SMEM_GEMM>>>(
        h1r, w1, b1, nullptr, act, nullptr, Hh, Ff, Ff);
    gemm_tc<false, E_RES_TRANS, false><<<dim3(Hh / BN, Mm / BM), blk, SMEM_GEMM>>>(
        act, w2, b2, h1, out, nullptr, Ff, Hh, Hh);
}

// round 16
// speedup vs baseline: 1.0330x; 1.0330x over previous
#include <cuda_runtime.h>
#include <cuda_bf16.h>
#include <math.h>
#include <stdint.h>

// Problem constants
constexpr int S_ = 256;
constexpr int Bb = 32;
constexpr int Hh = 512;
constexpr int Pp = 2048;
constexpr int Tt = Pp + S_;     // 2304
constexpr int Mm = Bb * S_;     // 8192
constexpr int Ff = 4 * Hh;      // 2048
constexpr int QKVN = 3 * Hh;    // 1536

constexpr float SCALE = 0.044194173824159223f;  // 1/sqrt(512)

// Scratch
__device__ float g_qkv[(size_t)Mm * QKVN];
__device__ float g_sc[(size_t)Mm * Tt];            // unnormalized probs (p~)
__device__ float g_rp[(size_t)Bb * 4 * 36 * 64];   // row partial sums
__device__ float g_at[(size_t)Mm * Hh];
__device__ float g_h1[(size_t)Mm * Hh];            // exact (residual)
__device__ float g_h1r[(size_t)Mm * Hh];           // rounded (FFN-A)
__device__ float g_act[(size_t)Mm * Ff];
// Pre-rounded inputs
__device__ float g_hr[(size_t)Mm * Hh];
__device__ float g_wqkv[Hh * QKVN];
__device__ float g_bqkv[QKVN];
__device__ float g_wo[Hh * Hh];
__device__ float g_w1[Hh * Ff];
__device__ float g_w2[Ff * Hh];

__device__ __forceinline__ size_t hid_off(int m) {
    int b = m >> 8;
    int s = m & (S_ - 1);
    return ((size_t)s * Bb + b) * Hh;
}

__device__ __forceinline__ float rnd_tf32(float x) {
    uint32_t u;
    asm("cvt.rna.tf32.f32 %0, %1;" : "=r"(u) : "f"(x));
    return __uint_as_float(u);
}

__device__ __forceinline__ void mma8(float* d, const uint32_t* a, const uint32_t* b) {
    asm volatile(
        "mma.sync.aligned.m16n8k8.row.col.f32.tf32.tf32.f32 "
        "{%0,%1,%2,%3},{%4,%5,%6,%7},{%8,%9},{%0,%1,%2,%3};"
        : "+f"(d[0]), "+f"(d[1]), "+f"(d[2]), "+f"(d[3])
        : "r"(a[0]), "r"(a[1]), "r"(a[2]), "r"(a[3]), "r"(b[0]), "r"(b[1]));
}

__device__ __forceinline__ void cp16(void* smem, const void* g) {
    uint32_t s = (uint32_t)__cvta_generic_to_shared(smem);
    asm volatile("cp.async.cg.shared.global [%0], [%1], 16;" :: "r"(s), "l"(g));
}
__device__ __forceinline__ void cp_commit() { asm volatile("cp.async.commit_group;"); }
template<int N>
__device__ __forceinline__ void cp_wait() { asm volatile("cp.async.wait_group %0;" :: "n"(N)); }

__device__ __forceinline__ uint32_t u32of(float f) { return __float_as_uint(f); }

#define BM 64
#define BN 128
#define BK 16
#define AKP 20
#define BNP 136
#define STG 4      // pipeline stages: dense GEMMs + PV
#define STS 3      // pipeline stages: scores
#define NT 128
#define OCC 4

enum { E_BIAS = 0, E_GELU = 1, E_RES_HID = 2, E_RES_TRANS = 3 };

constexpr int SMEM_GEMM   = STG * (BM * AKP + BK * BNP) * 4;   // 55296
constexpr int SMEM_SCORES = STS * (BM * AKP + BN * AKP) * 4;   // 46080

// ---------------------------------------------------------------------------
// Prep: round to tf32 (RNA), pack QKV weights+bias.
// ---------------------------------------------------------------------------
constexpr int F4_HR   = Mm * Hh / 4;
constexpr int F4_WO   = Hh * Hh / 4;
constexpr int F4_W1   = Hh * Ff / 4;
constexpr int F4_W2   = Ff * Hh / 4;
constexpr int F4_WQKV = Hh * QKVN / 4;
constexpr int F4_BQKV = QKVN / 4;
constexpr int F4_TOTAL = F4_HR + F4_WO + F4_W1 + F4_W2 + F4_WQKV + F4_BQKV;

__global__ __launch_bounds__(256)
void prep_kernel(const float* __restrict__ hidden,
                 const float* __restrict__ Wq, const float* __restrict__ Wk,
                 const float* __restrict__ Wv, const float* __restrict__ Wo,
                 const float* __restrict__ W1, const float* __restrict__ W2,
                 const float* __restrict__ bq, const float* __restrict__ bk,
                 const float* __restrict__ bv)
{
    int i = blockIdx.x * blockDim.x + threadIdx.x;
    if (i >= F4_TOTAL) return;

    auto rc = [](const float* s, float* d, int idx) {
        float4 v = reinterpret_cast<const float4*>(s)[idx];
        v.x = rnd_tf32(v.x); v.y = rnd_tf32(v.y);
        v.z = rnd_tf32(v.z); v.w = rnd_tf32(v.w);
        reinterpret_cast<float4*>(d)[idx] = v;
    };

    if (i < F4_HR) { rc(hidden, g_hr, i); return; }
    i -= F4_HR;
    if (i < F4_WO) { rc(Wo, g_wo, i); return; }
    i -= F4_WO;
    if (i < F4_W1) { rc(W1, g_w1, i); return; }
    i -= F4_W1;
    if (i < F4_W2) { rc(W2, g_w2, i); return; }
    i -= F4_W2;
    if (i < F4_WQKV) {
        int row = i / (QKVN / 4);
        int j4  = i % (QKVN / 4);
        int sel = j4 >> 7;
        int col4 = j4 & 127;
        const float* src = (sel == 0) ? Wq : (sel == 1) ? Wk : Wv;
        float4 v = reinterpret_cast<const float4*>(src + (size_t)row * Hh)[col4];
        v.x = rnd_tf32(v.x); v.y = rnd_tf32(v.y);
        v.z = rnd_tf32(v.z); v.w = rnd_tf32(v.w);
        reinterpret_cast<float4*>(g_wqkv + (size_t)row * QKVN)[j4] = v;
        return;
    }
    i -= F4_WQKV;
    {
        int sel = i >> 7;
        int col4 = i & 127;
        const float* src = (sel == 0) ? bq : (sel == 1) ? bk : bv;
        reinterpret_cast<float4*>(g_bqkv)[i] = reinterpret_cast<const float4*>(src)[col4];
    }
}

// ---------------------------------------------------------------------------
// 32x64 warp-tile mainloop core (4 warps => 64x128 CTA tile).
// ---------------------------------------------------------------------------
struct Frag {
    float acc[2][8][4];
    __device__ __forceinline__ void zero() {
        #pragma unroll
        for (int i = 0; i < 2; i++)
            #pragma unroll
            for (int j = 0; j < 8; j++)
                #pragma unroll
                for (int t = 0; t < 4; t++) acc[i][j][t] = 0.f;
    }
};

template<bool BKN>
__device__ __forceinline__ void tile_mma(Frag& F, const float* Ab, const float* Bbuf,
                                         int wm, int wn, int lr, int lc)
{
    #pragma unroll
    for (int ks = 0; ks < 2; ks++) {
        const int kk = ks * 8 + lc;
        uint32_t af[2][4];
        #pragma unroll
        for (int mt = 0; mt < 2; mt++) {
            int r = wm * 32 + mt * 16 + lr;
            af[mt][0] = u32of(Ab[r * AKP + kk]);
            af[mt][1] = u32of(Ab[(r + 8) * AKP + kk]);
            af[mt][2] = u32of(Ab[r * AKP + kk + 4]);
            af[mt][3] = u32of(Ab[(r + 8) * AKP + kk + 4]);
        }
        uint32_t bf[8][2];
        #pragma unroll
        for (int nt = 0; nt < 8; nt++) {
            int cc = wn * 64 + nt * 8 + lr;
            if (BKN) {
                bf[nt][0] = u32of(Bbuf[kk * BNP + cc]);
                bf[nt][1] = u32of(Bbuf[(kk + 4) * BNP + cc]);
            } else {
                bf[nt][0] = u32of(Bbuf[cc * AKP + kk]);
                bf[nt][1] = u32of(Bbuf[cc * AKP + kk + 4]);
            }
        }
        #pragma unroll
        for (int mt = 0; mt < 2; mt++)
            #pragma unroll
            for (int nt = 0; nt < 8; nt++)
                mma8(F.acc[mt][nt], af[mt], bf[nt]);
    }
}

// ---------------------------------------------------------------------------
// Standard GEMM (STG stages)
// ---------------------------------------------------------------------------
template<bool AHID, int EPI, bool ROUND>
__global__ __launch_bounds__(NT, OCC)
void gemm_tc(const float* __restrict__ A, const float* __restrict__ W,
             const float* __restrict__ bias, const float* __restrict__ R,
             float* __restrict__ C, float* __restrict__ C2, int K, int N, int CN)
{
    extern __shared__ float sm[];
    float* As = sm;
    float* Bs = sm + STG * BM * AKP;

    const int tid  = threadIdx.x;
    const int lane = tid & 31;
    const int warp = tid >> 5;
    const int wm   = warp & 1;
    const int wn   = warp >> 1;
    const int lr   = lane >> 2;
    const int lc   = lane & 3;
    const int m0   = blockIdx.y * BM;
    const int n0   = blockIdx.x * BN;
    const int KT   = K / BK;

    auto issue = [&](int kt) {
        int st = kt % STG;
        float* Ad = As + st * BM * AKP;
        float* Bd = Bs + st * BK * BNP;
        #pragma unroll
        for (int u = 0; u < 2; u++) {
            int c = tid + u * NT;
            int m = c >> 2, k4 = c & 3;
            const float* g = (AHID ? (A + hid_off(m0 + m)) : (A + (size_t)(m0 + m) * K))
                             + kt * BK + k4 * 4;
            cp16(Ad + m * AKP + k4 * 4, g);
        }
        #pragma unroll
        for (int u = 0; u < 4; u++) {
            int c = tid + u * NT;
            int k = c >> 5, n4 = c & 31;
            cp16(Bd + k * BNP + n4 * 4, W + (size_t)(kt * BK + k) * N + n0 + n4 * 4);
        }
        cp_commit();
    };

    Frag F; F.zero();

    #pragma unroll
    for (int p = 0; p < STG - 1; p++) issue(p);

    for (int kt = 0; kt < KT; ++kt) {
        cp_wait<STG - 2>();
        __syncthreads();
        tile_mma<true>(F, As + (kt % STG) * BM * AKP, Bs + (kt % STG) * BK * BNP,
                       wm, wn, lr, lc);
        if (kt + STG - 1 < KT) issue(kt + STG - 1); else cp_commit();
    }

    #pragma unroll
    for (int nt = 0; nt < 8; nt++) {
        int c = n0 + wn * 64 + nt * 8 + lc * 2;
        float bv0 = bias[c], bv1 = bias[c + 1];
        #pragma unroll
        for (int mt = 0; mt < 2; mt++) {
            int r0 = m0 + wm * 32 + mt * 16 + lr;
            int r1 = r0 + 8;
            float v00 = F.acc[mt][nt][0] + bv0;
            float v01 = F.acc[mt][nt][1] + bv1;
            float v10 = F.acc[mt][nt][2] + bv0;
            float v11 = F.acc[mt][nt][3] + bv1;
            if (EPI == E_GELU) {
                v00 = 0.5f * v00 * (1.f + erff(v00 * 0.70710678118654752f));
                v01 = 0.5f * v01 * (1.f + erff(v01 * 0.70710678118654752f));
                v10 = 0.5f * v10 * (1.f + erff(v10 * 0.70710678118654752f));
                v11 = 0.5f * v11 * (1.f + erff(v11 * 0.70710678118654752f));
            } else if (EPI == E_RES_HID) {
                const float* rp0 = R + hid_off(r0) + c;
                const float* rp1 = R + hid_off(r1) + c;
                v00 += rp0[0]; v01 += rp0[1];
                v10 += rp1[0]; v11 += rp1[1];
            } else if (EPI == E_RES_TRANS) {
                const float* rp0 = R + (size_t)r0 * CN + c;
                const float* rp1 = R + (size_t)r1 * CN + c;
                v00 += rp0[0]; v01 += rp0[1];
                v10 += rp1[0]; v11 += rp1[1];
            }
            if (EPI == E_RES_HID) {
                *reinterpret_cast<float2*>(C  + (size_t)r0 * CN + c) = make_float2(v00, v01);
                *reinterpret_cast<float2*>(C  + (size_t)r1 * CN + c) = make_float2(v10, v11);
                *reinterpret_cast<float2*>(C2 + (size_t)r0 * CN + c) =
                    make_float2(rnd_tf32(v00), rnd_tf32(v01));
                *reinterpret_cast<float2*>(C2 + (size_t)r1 * CN + c) =
                    make_float2(rnd_tf32(v10), rnd_tf32(v11));
            } else {
                if (ROUND) {
                    v00 = rnd_tf32(v00); v01 = rnd_tf32(v01);
                    v10 = rnd_tf32(v10); v11 = rnd_tf32(v11);
                }
                if (EPI == E_RES_TRANS) {
                    *reinterpret_cast<float2*>(C + hid_off(r0) + c) = make_float2(v00, v01);
                    *reinterpret_cast<float2*>(C + hid_off(r1) + c) = make_float2(v10, v11);
                } else {
                    *reinterpret_cast<float2*>(C + (size_t)r0 * CN + c) = make_float2(v00, v01);
                    *reinterpret_cast<float2*>(C + (size_t)r1 * CN + c) = make_float2(v10, v11);
                }
            }
        }
    }
}

// ---------------------------------------------------------------------------
// Scores (STS stages): unnormalized p~ + row partial sums.
// R13 grid order (b = blockIdx.z — preserves L2 locality of co-resident CTAs).
// Dead tiles: the zeroed score region is NEVER read by pv (pv's k-tile sets
// stop inside live tiles), so dead CTAs skip the zero stores and only zero
// their rpart slots.
// g_rp layout: [b][mtile(4)][slot(36 = ntile*2 + wn)][row(64)]
// ---------------------------------------------------------------------------
__global__ __launch_bounds__(NT, OCC)
void scores_tc(const float* __restrict__ qkv, const float* __restrict__ past_k,
               const int* __restrict__ past_lens, float* __restrict__ scores,
               float* __restrict__ rpart)
{
    extern __shared__ float sm[];
    float* As = sm;
    float* Bs = sm + STS * BM * AKP;

    const int tid  = threadIdx.x;
    const int lane = tid & 31;
    const int warp = tid >> 5;
    const int wm   = warp & 1;
    const int wn   = warp >> 1;
    const int lr   = lane >> 2;
    const int lc   = lane & 3;
    const int b    = blockIdx.z;
    const int m0   = blockIdx.y * BM;
    const int n0   = blockIdx.x * BN;
    const int KT   = Hh / BK;

    const int L = past_lens[b];
    float* rpb = rpart + ((size_t)(b * 4 + (m0 >> 6)) * 36 + (n0 >> 7) * 2) * 64;

    bool dead = (n0 + BN <= Pp) ? (n0 >= L)
              : ((n0 >= Pp) && (n0 - Pp) > m0 + BM - 1);
    if (dead) {
        rpb[tid] = 0.f;   // 128 threads cover both 64-row slots; scores unwritten (never read)
        return;
    }

    const float* Aq = qkv + (size_t)b * S_ * QKVN;

    auto keyrow = [&](int j) -> const float* {
        return (j < Pp) ? (past_k + ((size_t)b * Pp + j) * Hh)
                        : (qkv + ((size_t)b * S_ + (j - Pp)) * QKVN + Hh);
    };
    auto issue = [&](int kt) {
        int st = kt % STS;
        float* Ad = As + st * BM * AKP;
        float* Bd = Bs + st * BN * AKP;
        #pragma unroll
        for (int u = 0; u < 2; u++) {
            int c = tid + u * NT;
            int m = c >> 2, k4 = c & 3;
            cp16(Ad + m * AKP + k4 * 4, Aq + (size_t)(m0 + m) * QKVN + kt * BK + k4 * 4);
        }
        #pragma unroll
        for (int u = 0; u < 4; u++) {
            int c = tid + u * NT;
            int n = c >> 2, k4 = c & 3;
            cp16(Bd + n * AKP + k4 * 4, keyrow(n0 + n) + kt * BK + k4 * 4);
        }
        cp_commit();
    };

    Frag F; F.zero();

    #pragma unroll
    for (int p = 0; p < STS - 1; p++) issue(p);

    for (int kt = 0; kt < KT; ++kt) {
        cp_wait<STS - 2>();
        __syncthreads();
        tile_mma<false>(F, As + (kt % STS) * BM * AKP, Bs + (kt % STS) * BN * AKP,
                        wm, wn, lr, lc);
        if (kt + STS - 1 < KT) issue(kt + STS - 1); else cp_commit();
    }

    float rsum[4];
    #pragma unroll
    for (int i = 0; i < 4; i++) rsum[i] = 0.f;

    #pragma unroll
    for (int mt = 0; mt < 2; mt++)
        #pragma unroll
        for (int nt = 0; nt < 8; nt++) {
            int c = n0 + wn * 64 + nt * 8 + lc * 2;
            #pragma unroll
            for (int half = 0; half < 2; half++) {
                int s = m0 + wm * 32 + mt * 16 + lr + half * 8;
                float v0 = F.acc[mt][nt][half * 2 + 0];
                float v1 = F.acc[mt][nt][half * 2 + 1];
                bool ok0 = (c < Pp) ? (c < L) : ((c - Pp) <= s);
                int c1 = c + 1;
                bool ok1 = (c1 < Pp) ? (c1 < L) : ((c1 - Pp) <= s);
                float e0 = ok0 ? rnd_tf32(__expf(v0 * SCALE)) : 0.f;
                float e1 = ok1 ? rnd_tf32(__expf(v1 * SCALE)) : 0.f;
                rsum[mt * 2 + half] += e0 + e1;
                *reinterpret_cast<float2*>(scores + ((size_t)b * S_ + s) * Tt + c) =
                    make_float2(e0, e1);
            }
        }

    #pragma unroll
    for (int i = 0; i < 4; i++) {
        float v = rsum[i];
        v += __shfl_xor_sync(0xffffffffu, v, 1);
        v += __shfl_xor_sync(0xffffffffu, v, 2);
        rsum[i] = v;
    }
    if (lc == 0) {
        #pragma unroll
        for (int mt = 0; mt < 2; mt++)
            #pragma unroll
            for (int half = 0; half < 2; half++) {
                int rowl = wm * 32 + mt * 16 + lr + half * 8;
                rpb[wn * 64 + rowl] = rsum[mt * 2 + half];
            }
    }
}

// ---------------------------------------------------------------------------
// PV (STG stages): attn = (p~ @ V_all) / rowsum, k-tile skipping.
// R13 grid order (b = blockIdx.z).
// ---------------------------------------------------------------------------
__global__ __launch_bounds__(NT, OCC)
void pv_tc(const float* __restrict__ probs, const float* __restrict__ past_v,
           const float* __restrict__ qkv, float* __restrict__ attn,
           const int* __restrict__ past_lens, const float* __restrict__ rpart)
{
    extern __shared__ float sm[];
    float* As = sm;
    float* Bs = sm + STG * BM * AKP;
    __shared__ float sinv[BM];

    const int tid  = threadIdx.x;
    const int lane = tid & 31;
    const int warp = tid >> 5;
    const int wm   = warp & 1;
    const int wn   = warp >> 1;
    const int lr   = lane >> 2;
    const int lc   = lane & 3;
    const int b    = blockIdx.z;
    const int m0   = blockIdx.y * BM;
    const int n0   = blockIdx.x * BN;

    if (tid < BM) {
        const float* rp = rpart + (size_t)(b * 4 + (m0 >> 6)) * 36 * 64 + tid;
        float s = 0.f;
        #pragma unroll
        for (int t = 0; t < 36; t++) s += rp[t * 64];
        sinv[tid] = 1.f / s;
    }

    const int L  = past_lens[b];
    const int ne = (L + 15) >> 4;
    const int nn = (m0 >> 4) + 4;
    const int total = ne + nn;

    const float* Ap = probs + (size_t)b * S_ * Tt;

    auto kmap = [&](int i) { return (i < ne) ? i : 128 + (i - ne); };
    auto vrow = [&](int kidx) -> const float* {
        return (kidx < Pp) ? (past_v + ((size_t)b * Pp + kidx) * Hh)
                           : (qkv + ((size_t)b * S_ + (kidx - Pp)) * QKVN + 2 * Hh);
    };
    auto issue = [&](int i) {
        int kt = kmap(i);
        int st = i % STG;
        float* Ad = As + st * BM * AKP;
        float* Bd = Bs + st * BK * BNP;
        #pragma unroll
        for (int u = 0; u < 2; u++) {
            int c = tid + u * NT;
            int m = c >> 2, k4 = c & 3;
            cp16(Ad + m * AKP + k4 * 4, Ap + (size_t)(m0 + m) * Tt + kt * BK + k4 * 4);
        }
        #pragma unroll
        for (int u = 0; u < 4; u++) {
            int c = tid + u * NT;
            int k = c >> 5, n4 = c & 31;
            cp16(Bd + k * BNP + n4 * 4, vrow(kt * BK + k) + n0 + n4 * 4);
        }
        cp_commit();
    };

    Frag F; F.zero();

    #pragma unroll
    for (int p = 0; p < STG - 1; p++) if (p < total) issue(p);

    for (int i = 0; i < total; ++i) {
        cp_wait<STG - 2>();
        __syncthreads();
        tile_mma<true>(F, As + (i % STG) * BM * AKP, Bs + (i % STG) * BK * BNP,
                       wm, wn, lr, lc);
        if (i + STG - 1 < total) issue(i + STG - 1); else cp_commit();
    }
    __syncthreads();

    #pragma unroll
    for (int mt = 0; mt < 2; mt++)
        #pragma unroll
        for (int nt = 0; nt < 8; nt++) {
            int c = n0 + wn * 64 + nt * 8 + lc * 2;
            int rl0 = wm * 32 + mt * 16 + lr;
            int rl1 = rl0 + 8;
            int r0 = m0 + rl0;
            int r1 = m0 + rl1;
            float i0 = sinv[rl0], i1 = sinv[rl1];
            *reinterpret_cast<float2*>(attn + ((size_t)b * S_ + r0) * Hh + c) =
                make_float2(rnd_tf32(F.acc[mt][nt][0] * i0), rnd_tf32(F.acc[mt][nt][1] * i0));
            *reinterpret_cast<float2*>(attn + ((size_t)b * S_ + r1) * Hh + c) =
                make_float2(rnd_tf32(F.acc[mt][nt][2] * i1), rnd_tf32(F.acc[mt][nt][3] * i1));
        }
}

// ---------------------------------------------------------------------------
// Launch
// ---------------------------------------------------------------------------
extern "C" void kernel_launch(void* const* d_in, const int* in_sizes, int n_in,
                              void* d_out, int out_size)
{
    const float* hidden    = (const float*)d_in[0];
    const float* past_k    = (const float*)d_in[1];
    const float* past_v    = (const float*)d_in[2];
    const int*   past_lens = (const int*)  d_in[3];
    const float* Wq = (const float*)d_in[4];  const float* bq = (const float*)d_in[5];
    const float* Wk = (const float*)d_in[6];  const float* bk = (const float*)d_in[7];
    const float* Wv = (const float*)d_in[8];  const float* bv = (const float*)d_in[9];
    const float* Wo = (const float*)d_in[10]; const float* bo = (const float*)d_in[11];
    const float* W1 = (const float*)d_in[12]; const float* b1 = (const float*)d_in[13];
    const float* W2 = (const float*)d_in[14]; const float* b2 = (const float*)d_in[15];
    float* out = (float*)d_out;

    float *qkv, *sc, *rp, *at, *h1, *h1r, *act, *hr, *wqkv, *bqkv, *wo, *w1, *w2;
    cudaGetSymbolAddress((void**)&qkv,  g_qkv);
    cudaGetSymbolAddress((void**)&sc,   g_sc);
    cudaGetSymbolAddress((void**)&rp,   g_rp);
    cudaGetSymbolAddress((void**)&at,   g_at);
    cudaGetSymbolAddress((void**)&h1,   g_h1);
    cudaGetSymbolAddress((void**)&h1r,  g_h1r);
    cudaGetSymbolAddress((void**)&act,  g_act);
    cudaGetSymbolAddress((void**)&hr,   g_hr);
    cudaGetSymbolAddress((void**)&wqkv, g_wqkv);
    cudaGetSymbolAddress((void**)&bqkv, g_bqkv);
    cudaGetSymbolAddress((void**)&wo,   g_wo);
    cudaGetSymbolAddress((void**)&w1,   g_w1);
    cudaGetSymbolAddress((void**)&w2,   g_w2);

    cudaFuncSetAttribute(gemm_tc<true,  E_BIAS,      true >, cudaFuncAttributeMaxDynamicSharedMemorySize, SMEM_GEMM);
    cudaFuncSetAttribute(gemm_tc<false, E_RES_HID,   false>, cudaFuncAttributeMaxDynamicSharedMemorySize, SMEM_GEMM);
    cudaFuncSetAttribute(gemm_tc<false, E_GELU,      true >, cudaFuncAttributeMaxDynamicSharedMemorySize, SMEM_GEMM);
    cudaFuncSetAttribute(gemm_tc<false, E_RES_TRANS, false>, cudaFuncAttributeMaxDynamicSharedMemorySize, SMEM_GEMM);
    cudaFuncSetAttribute(scores_tc, cudaFuncAttributeMaxDynamicSharedMemorySize, SMEM_SCORES);
    cudaFuncSetAttribute(pv_tc,     cudaFuncAttributeMaxDynamicSharedMemorySize, SMEM_GEMM);

    prep_kernel<<<(F4_TOTAL + 255) / 256, 256>>>(hidden, Wq, Wk, Wv, Wo, W1, W2, bq, bk, bv);

    dim3 blk(NT);

    gemm_tc<true, E_BIAS, true><<<dim3(QKVN / BN, Mm / BM), blk, SMEM_GEMM>>>(
        hr, wqkv, bqkv, nullptr, qkv, nullptr, Hh, QKVN, QKVN);

    scores_tc<<<dim3(Tt / BN, S_ / BM, Bb), blk, SMEM_SCORES>>>(qkv, past_k, past_lens, sc, rp);
    pv_tc<<<dim3(Hh / BN, S_ / BM, Bb), blk, SMEM_GEMM>>>(sc, past_v, qkv, at, past_lens, rp);

    gemm_tc<false, E_RES_HID, false><<<dim3(Hh / BN, Mm / BM), blk, SMEM_GEMM>>>(
        at, wo, bo, hidden, h1, h1r, Hh, Hh, Hh);

    gemm_tc<false, E_GELU, true><<<dim3(Ff / BN, Mm / BM), blk, SMEM_GEMM>>>(
        h1r, w1, b1, nullptr, act, nullptr, Hh, Ff, Ff);
    gemm_tc<false, E_RES_TRANS, false><<<dim3(Hh / BN, Mm / BM), blk, SMEM_GEMM>>>(
        act, w2, b2, h1, out, nullptr, Ff, Hh, Hh);
}

// round 17
// speedup vs baseline: 1.0456x; 1.0122x over previous
#include <cuda_runtime.h>
#include <cuda_bf16.h>
#include <math.h>
#include <stdint.h>

// Problem constants
constexpr int S_ = 256;
constexpr int Bb = 32;
constexpr int Hh = 512;
constexpr int Pp = 2048;
constexpr int Tt = Pp + S_;     // 2304
constexpr int Mm = Bb * S_;     // 8192
constexpr int Ff = 4 * Hh;      // 2048
constexpr int QKVN = 3 * Hh;    // 1536

constexpr float SCALE = 0.044194173824159223f;  // 1/sqrt(512)

// Scratch
__device__ float g_qkv[(size_t)Mm * QKVN];
__device__ float g_sc[(size_t)Mm * Tt];            // unnormalized probs (p~)
__device__ float g_rp[(size_t)Bb * 4 * 36 * 64];   // row partial sums
__device__ float g_at[(size_t)Mm * Hh];
__device__ float g_h1r[(size_t)Mm * Hh];           // rounded h1 (FFN-A + residual)
__device__ float g_act[(size_t)Mm * Ff];
// Pre-rounded inputs
__device__ float g_hr[(size_t)Mm * Hh];
__device__ float g_wqkv[Hh * QKVN];
__device__ float g_bqkv[QKVN];
__device__ float g_wo[Hh * Hh];
__device__ float g_w1[Hh * Ff];
__device__ float g_w2[Ff * Hh];

__device__ __forceinline__ size_t hid_off(int m) {
    int b = m >> 8;
    int s = m & (S_ - 1);
    return ((size_t)s * Bb + b) * Hh;
}

__device__ __forceinline__ float rnd_tf32(float x) {
    uint32_t u;
    asm("cvt.rna.tf32.f32 %0, %1;" : "=r"(u) : "f"(x));
    return __uint_as_float(u);
}

__device__ __forceinline__ void mma8(float* d, const uint32_t* a, const uint32_t* b) {
    asm volatile(
        "mma.sync.aligned.m16n8k8.row.col.f32.tf32.tf32.f32 "
        "{%0,%1,%2,%3},{%4,%5,%6,%7},{%8,%9},{%0,%1,%2,%3};"
        : "+f"(d[0]), "+f"(d[1]), "+f"(d[2]), "+f"(d[3])
        : "r"(a[0]), "r"(a[1]), "r"(a[2]), "r"(a[3]), "r"(b[0]), "r"(b[1]));
}

__device__ __forceinline__ void cp16(void* smem, const void* g) {
    uint32_t s = (uint32_t)__cvta_generic_to_shared(smem);
    asm volatile("cp.async.cg.shared.global [%0], [%1], 16;" :: "r"(s), "l"(g));
}
__device__ __forceinline__ void cp_commit() { asm volatile("cp.async.commit_group;"); }
template<int N>
__device__ __forceinline__ void cp_wait() { asm volatile("cp.async.wait_group %0;" :: "n"(N)); }

__device__ __forceinline__ uint32_t u32of(float f) { return __float_as_uint(f); }

#define BM 64
#define BN 128
#define BK 16
#define AKP 20
#define BNP 136
#define STG 4      // pipeline stages: dense GEMMs + PV
#define STS 3      // pipeline stages: scores
#define NT 128
#define OCC 4

enum { E_BIAS = 0, E_GELU = 1, E_RES_HID = 2, E_RES_TRANS = 3 };

constexpr int SMEM_GEMM   = STG * (BM * AKP + BK * BNP) * 4;   // 55296
constexpr int SMEM_SCORES = STS * (BM * AKP + BN * AKP) * 4;   // 46080

// ---------------------------------------------------------------------------
// Prep: round to tf32 (RNA), pack QKV weights+bias.
// ---------------------------------------------------------------------------
constexpr int F4_HR   = Mm * Hh / 4;
constexpr int F4_WO   = Hh * Hh / 4;
constexpr int F4_W1   = Hh * Ff / 4;
constexpr int F4_W2   = Ff * Hh / 4;
constexpr int F4_WQKV = Hh * QKVN / 4;
constexpr int F4_BQKV = QKVN / 4;
constexpr int F4_TOTAL = F4_HR + F4_WO + F4_W1 + F4_W2 + F4_WQKV + F4_BQKV;

__global__ __launch_bounds__(256)
void prep_kernel(const float* __restrict__ hidden,
                 const float* __restrict__ Wq, const float* __restrict__ Wk,
                 const float* __restrict__ Wv, const float* __restrict__ Wo,
                 const float* __restrict__ W1, const float* __restrict__ W2,
                 const float* __restrict__ bq, const float* __restrict__ bk,
                 const float* __restrict__ bv)
{
    int i = blockIdx.x * blockDim.x + threadIdx.x;
    if (i >= F4_TOTAL) return;

    auto rc = [](const float* s, float* d, int idx) {
        float4 v = reinterpret_cast<const float4*>(s)[idx];
        v.x = rnd_tf32(v.x); v.y = rnd_tf32(v.y);
        v.z = rnd_tf32(v.z); v.w = rnd_tf32(v.w);
        reinterpret_cast<float4*>(d)[idx] = v;
    };

    if (i < F4_HR) { rc(hidden, g_hr, i); return; }
    i -= F4_HR;
    if (i < F4_WO) { rc(Wo, g_wo, i); return; }
    i -= F4_WO;
    if (i < F4_W1) { rc(W1, g_w1, i); return; }
    i -= F4_W1;
    if (i < F4_W2) { rc(W2, g_w2, i); return; }
    i -= F4_W2;
    if (i < F4_WQKV) {
        int row = i / (QKVN / 4);
        int j4  = i % (QKVN / 4);
        int sel = j4 >> 7;
        int col4 = j4 & 127;
        const float* src = (sel == 0) ? Wq : (sel == 1) ? Wk : Wv;
        float4 v = reinterpret_cast<const float4*>(src + (size_t)row * Hh)[col4];
        v.x = rnd_tf32(v.x); v.y = rnd_tf32(v.y);
        v.z = rnd_tf32(v.z); v.w = rnd_tf32(v.w);
        reinterpret_cast<float4*>(g_wqkv + (size_t)row * QKVN)[j4] = v;
        return;
    }
    i -= F4_WQKV;
    {
        int sel = i >> 7;
        int col4 = i & 127;
        const float* src = (sel == 0) ? bq : (sel == 1) ? bk : bv;
        reinterpret_cast<float4*>(g_bqkv)[i] = reinterpret_cast<const float4*>(src)[col4];
    }
}

// ---------------------------------------------------------------------------
// 32x64 warp-tile mainloop core (4 warps => 64x128 CTA tile).
// ---------------------------------------------------------------------------
struct Frag {
    float acc[2][8][4];
    __device__ __forceinline__ void zero() {
        #pragma unroll
        for (int i = 0; i < 2; i++)
            #pragma unroll
            for (int j = 0; j < 8; j++)
                #pragma unroll
                for (int t = 0; t < 4; t++) acc[i][j][t] = 0.f;
    }
};

template<bool BKN>
__device__ __forceinline__ void tile_mma(Frag& F, const float* Ab, const float* Bbuf,
                                         int wm, int wn, int lr, int lc)
{
    #pragma unroll
    for (int ks = 0; ks < 2; ks++) {
        const int kk = ks * 8 + lc;
        uint32_t af[2][4];
        #pragma unroll
        for (int mt = 0; mt < 2; mt++) {
            int r = wm * 32 + mt * 16 + lr;
            af[mt][0] = u32of(Ab[r * AKP + kk]);
            af[mt][1] = u32of(Ab[(r + 8) * AKP + kk]);
            af[mt][2] = u32of(Ab[r * AKP + kk + 4]);
            af[mt][3] = u32of(Ab[(r + 8) * AKP + kk + 4]);
        }
        uint32_t bf[8][2];
        #pragma unroll
        for (int nt = 0; nt < 8; nt++) {
            int cc = wn * 64 + nt * 8 + lr;
            if (BKN) {
                bf[nt][0] = u32of(Bbuf[kk * BNP + cc]);
                bf[nt][1] = u32of(Bbuf[(kk + 4) * BNP + cc]);
            } else {
                bf[nt][0] = u32of(Bbuf[cc * AKP + kk]);
                bf[nt][1] = u32of(Bbuf[cc * AKP + kk + 4]);
            }
        }
        #pragma unroll
        for (int mt = 0; mt < 2; mt++)
            #pragma unroll
            for (int nt = 0; nt < 8; nt++)
                mma8(F.acc[mt][nt], af[mt], bf[nt]);
    }
}

// ---------------------------------------------------------------------------
// Standard GEMM (STG stages).
// E_RES_HID: writes ONE buffer = rnd_tf32(acc + bias + residual) — used both
// as FFN1 A-operand and as FFN2 residual (saves a 16MB exact-copy store).
// ---------------------------------------------------------------------------
template<bool AHID, int EPI, bool ROUND>
__global__ __launch_bounds__(NT, OCC)
void gemm_tc(const float* __restrict__ A, const float* __restrict__ W,
             const float* __restrict__ bias, const float* __restrict__ R,
             float* __restrict__ C, int K, int N, int CN)
{
    extern __shared__ float sm[];
    float* As = sm;
    float* Bs = sm + STG * BM * AKP;

    const int tid  = threadIdx.x;
    const int lane = tid & 31;
    const int warp = tid >> 5;
    const int wm   = warp & 1;
    const int wn   = warp >> 1;
    const int lr   = lane >> 2;
    const int lc   = lane & 3;
    const int m0   = blockIdx.y * BM;
    const int n0   = blockIdx.x * BN;
    const int KT   = K / BK;

    auto issue = [&](int kt) {
        int st = kt % STG;
        float* Ad = As + st * BM * AKP;
        float* Bd = Bs + st * BK * BNP;
        #pragma unroll
        for (int u = 0; u < 2; u++) {
            int c = tid + u * NT;
            int m = c >> 2, k4 = c & 3;
            const float* g = (AHID ? (A + hid_off(m0 + m)) : (A + (size_t)(m0 + m) * K))
                             + kt * BK + k4 * 4;
            cp16(Ad + m * AKP + k4 * 4, g);
        }
        #pragma unroll
        for (int u = 0; u < 4; u++) {
            int c = tid + u * NT;
            int k = c >> 5, n4 = c & 31;
            cp16(Bd + k * BNP + n4 * 4, W + (size_t)(kt * BK + k) * N + n0 + n4 * 4);
        }
        cp_commit();
    };

    Frag F; F.zero();

    #pragma unroll
    for (int p = 0; p < STG - 1; p++) issue(p);

    for (int kt = 0; kt < KT; ++kt) {
        cp_wait<STG - 2>();
        __syncthreads();
        tile_mma<true>(F, As + (kt % STG) * BM * AKP, Bs + (kt % STG) * BK * BNP,
                       wm, wn, lr, lc);
        if (kt + STG - 1 < KT) issue(kt + STG - 1); else cp_commit();
    }

    #pragma unroll
    for (int nt = 0; nt < 8; nt++) {
        int c = n0 + wn * 64 + nt * 8 + lc * 2;
        float bv0 = bias[c], bv1 = bias[c + 1];
        #pragma unroll
        for (int mt = 0; mt < 2; mt++) {
            int r0 = m0 + wm * 32 + mt * 16 + lr;
            int r1 = r0 + 8;
            float v00 = F.acc[mt][nt][0] + bv0;
            float v01 = F.acc[mt][nt][1] + bv1;
            float v10 = F.acc[mt][nt][2] + bv0;
            float v11 = F.acc[mt][nt][3] + bv1;
            if (EPI == E_GELU) {
                v00 = 0.5f * v00 * (1.f + erff(v00 * 0.70710678118654752f));
                v01 = 0.5f * v01 * (1.f + erff(v01 * 0.70710678118654752f));
                v10 = 0.5f * v10 * (1.f + erff(v10 * 0.70710678118654752f));
                v11 = 0.5f * v11 * (1.f + erff(v11 * 0.70710678118654752f));
            } else if (EPI == E_RES_HID) {
                const float* rp0 = R + hid_off(r0) + c;
                const float* rp1 = R + hid_off(r1) + c;
                v00 += rp0[0]; v01 += rp0[1];
                v10 += rp1[0]; v11 += rp1[1];
            } else if (EPI == E_RES_TRANS) {
                const float* rp0 = R + (size_t)r0 * CN + c;
                const float* rp1 = R + (size_t)r1 * CN + c;
                v00 += rp0[0]; v01 += rp0[1];
                v10 += rp1[0]; v11 += rp1[1];
            }
            if (ROUND || EPI == E_RES_HID) {
                v00 = rnd_tf32(v00); v01 = rnd_tf32(v01);
                v10 = rnd_tf32(v10); v11 = rnd_tf32(v11);
            }
            if (EPI == E_RES_TRANS) {
                *reinterpret_cast<float2*>(C + hid_off(r0) + c) = make_float2(v00, v01);
                *reinterpret_cast<float2*>(C + hid_off(r1) + c) = make_float2(v10, v11);
            } else {
                *reinterpret_cast<float2*>(C + (size_t)r0 * CN + c) = make_float2(v00, v01);
                *reinterpret_cast<float2*>(C + (size_t)r1 * CN + c) = make_float2(v10, v11);
            }
        }
    }
}

// ---------------------------------------------------------------------------
// Scores (STS stages): unnormalized p~ + row partial sums.
// Dead tiles skip score stores (region never read by pv); only rpart zeroed.
// g_rp layout: [b][mtile(4)][slot(36 = ntile*2 + wn)][row(64)]
// ---------------------------------------------------------------------------
__global__ __launch_bounds__(NT, OCC)
void scores_tc(const float* __restrict__ qkv, const float* __restrict__ past_k,
               const int* __restrict__ past_lens, float* __restrict__ scores,
               float* __restrict__ rpart)
{
    extern __shared__ float sm[];
    float* As = sm;
    float* Bs = sm + STS * BM * AKP;

    const int tid  = threadIdx.x;
    const int lane = tid & 31;
    const int warp = tid >> 5;
    const int wm   = warp & 1;
    const int wn   = warp >> 1;
    const int lr   = lane >> 2;
    const int lc   = lane & 3;
    const int b    = blockIdx.z;
    const int m0   = blockIdx.y * BM;
    const int n0   = blockIdx.x * BN;
    const int KT   = Hh / BK;

    const int L = past_lens[b];
    float* rpb = rpart + ((size_t)(b * 4 + (m0 >> 6)) * 36 + (n0 >> 7) * 2) * 64;

    bool dead = (n0 + BN <= Pp) ? (n0 >= L)
              : ((n0 >= Pp) && (n0 - Pp) > m0 + BM - 1);
    if (dead) {
        rpb[tid] = 0.f;
        return;
    }

    const float* Aq = qkv + (size_t)b * S_ * QKVN;

    auto keyrow = [&](int j) -> const float* {
        return (j < Pp) ? (past_k + ((size_t)b * Pp + j) * Hh)
                        : (qkv + ((size_t)b * S_ + (j - Pp)) * QKVN + Hh);
    };
    auto issue = [&](int kt) {
        int st = kt % STS;
        float* Ad = As + st * BM * AKP;
        float* Bd = Bs + st * BN * AKP;
        #pragma unroll
        for (int u = 0; u < 2; u++) {
            int c = tid + u * NT;
            int m = c >> 2, k4 = c & 3;
            cp16(Ad + m * AKP + k4 * 4, Aq + (size_t)(m0 + m) * QKVN + kt * BK + k4 * 4);
        }
        #pragma unroll
        for (int u = 0; u < 4; u++) {
            int c = tid + u * NT;
            int n = c >> 2, k4 = c & 3;
            cp16(Bd + n * AKP + k4 * 4, keyrow(n0 + n) + kt * BK + k4 * 4);
        }
        cp_commit();
    };

    Frag F; F.zero();

    #pragma unroll
    for (int p = 0; p < STS - 1; p++) issue(p);

    for (int kt = 0; kt < KT; ++kt) {
        cp_wait<STS - 2>();
        __syncthreads();
        tile_mma<false>(F, As + (kt % STS) * BM * AKP, Bs + (kt % STS) * BN * AKP,
                        wm, wn, lr, lc);
        if (kt + STS - 1 < KT) issue(kt + STS - 1); else cp_commit();
    }

    float rsum[4];
    #pragma unroll
    for (int i = 0; i < 4; i++) rsum[i] = 0.f;

    #pragma unroll
    for (int mt = 0; mt < 2; mt++)
        #pragma unroll
        for (int nt = 0; nt < 8; nt++) {
            int c = n0 + wn * 64 + nt * 8 + lc * 2;
            #pragma unroll
            for (int half = 0; half < 2; half++) {
                int s = m0 + wm * 32 + mt * 16 + lr + half * 8;
                float v0 = F.acc[mt][nt][half * 2 + 0];
                float v1 = F.acc[mt][nt][half * 2 + 1];
                bool ok0 = (c < Pp) ? (c < L) : ((c - Pp) <= s);
                int c1 = c + 1;
                bool ok1 = (c1 < Pp) ? (c1 < L) : ((c1 - Pp) <= s);
                float e0 = ok0 ? rnd_tf32(__expf(v0 * SCALE)) : 0.f;
                float e1 = ok1 ? rnd_tf32(__expf(v1 * SCALE)) : 0.f;
                rsum[mt * 2 + half] += e0 + e1;
                *reinterpret_cast<float2*>(scores + ((size_t)b * S_ + s) * Tt + c) =
                    make_float2(e0, e1);
            }
        }

    #pragma unroll
    for (int i = 0; i < 4; i++) {
        float v = rsum[i];
        v += __shfl_xor_sync(0xffffffffu, v, 1);
        v += __shfl_xor_sync(0xffffffffu, v, 2);
        rsum[i] = v;
    }
    if (lc == 0) {
        #pragma unroll
        for (int mt = 0; mt < 2; mt++)
            #pragma unroll
            for (int half = 0; half < 2; half++) {
                int rowl = wm * 32 + mt * 16 + lr + half * 8;
                rpb[wn * 64 + rowl] = rsum[mt * 2 + half];
            }
    }
}

// ---------------------------------------------------------------------------
// PV (STG stages): heavy-first m ordering (LPT) — high-m0 CTAs (most k-tiles)
// launch first so short CTAs fill the drain tail.
// ---------------------------------------------------------------------------
__global__ __launch_bounds__(NT, OCC)
void pv_tc(const float* __restrict__ probs, const float* __restrict__ past_v,
           const float* __restrict__ qkv, float* __restrict__ attn,
           const int* __restrict__ past_lens, const float* __restrict__ rpart)
{
    extern __shared__ float sm[];
    float* As = sm;
    float* Bs = sm + STG * BM * AKP;
    __shared__ float sinv[BM];

    const int tid  = threadIdx.x;
    const int lane = tid & 31;
    const int warp = tid >> 5;
    const int wm   = warp & 1;
    const int wn   = warp >> 1;
    const int lr   = lane >> 2;
    const int lc   = lane & 3;
    const int b    = blockIdx.z;
    const int m0   = (gridDim.y - 1 - blockIdx.y) * BM;   // heavy-first
    const int n0   = blockIdx.x * BN;

    if (tid < BM) {
        const float* rp = rpart + (size_t)(b * 4 + (m0 >> 6)) * 36 * 64 + tid;
        float s = 0.f;
        #pragma unroll
        for (int t = 0; t < 36; t++) s += rp[t * 64];
        sinv[tid] = 1.f / s;
    }

    const int L  = past_lens[b];
    const int ne = (L + 15) >> 4;
    const int nn = (m0 >> 4) + 4;
    const int total = ne + nn;

    const float* Ap = probs + (size_t)b * S_ * Tt;

    auto kmap = [&](int i) { return (i < ne) ? i : 128 + (i - ne); };
    auto vrow = [&](int kidx) -> const float* {
        return (kidx < Pp) ? (past_v + ((size_t)b * Pp + kidx) * Hh)
                           : (qkv + ((size_t)b * S_ + (kidx - Pp)) * QKVN + 2 * Hh);
    };
    auto issue = [&](int i) {
        int kt = kmap(i);
        int st = i % STG;
        float* Ad = As + st * BM * AKP;
        float* Bd = Bs + st * BK * BNP;
        #pragma unroll
        for (int u = 0; u < 2; u++) {
            int c = tid + u * NT;
            int m = c >> 2, k4 = c & 3;
            cp16(Ad + m * AKP + k4 * 4, Ap + (size_t)(m0 + m) * Tt + kt * BK + k4 * 4);
        }
        #pragma unroll
        for (int u = 0; u < 4; u++) {
            int c = tid + u * NT;
            int k = c >> 5, n4 = c & 31;
            cp16(Bd + k * BNP + n4 * 4, vrow(kt * BK + k) + n0 + n4 * 4);
        }
        cp_commit();
    };

    Frag F; F.zero();

    #pragma unroll
    for (int p = 0; p < STG - 1; p++) if (p < total) issue(p);

    for (int i = 0; i < total; ++i) {
        cp_wait<STG - 2>();
        __syncthreads();
        tile_mma<true>(F, As + (i % STG) * BM * AKP, Bs + (i % STG) * BK * BNP,
                       wm, wn, lr, lc);
        if (i + STG - 1 < total) issue(i + STG - 1); else cp_commit();
    }
    __syncthreads();

    #pragma unroll
    for (int mt = 0; mt < 2; mt++)
        #pragma unroll
        for (int nt = 0; nt < 8; nt++) {
            int c = n0 + wn * 64 + nt * 8 + lc * 2;
            int rl0 = wm * 32 + mt * 16 + lr;
            int rl1 = rl0 + 8;
            int r0 = m0 + rl0;
            int r1 = m0 + rl1;
            float i0 = sinv[rl0], i1 = sinv[rl1];
            *reinterpret_cast<float2*>(attn + ((size_t)b * S_ + r0) * Hh + c) =
                make_float2(rnd_tf32(F.acc[mt][nt][0] * i0), rnd_tf32(F.acc[mt][nt][1] * i0));
            *reinterpret_cast<float2*>(attn + ((size_t)b * S_ + r1) * Hh + c) =
                make_float2(rnd_tf32(F.acc[mt][nt][2] * i1), rnd_tf32(F.acc[mt][nt][3] * i1));
        }
}

// ---------------------------------------------------------------------------
// Launch
// ---------------------------------------------------------------------------
extern "C" void kernel_launch(void* const* d_in, const int* in_sizes, int n_in,
                              void* d_out, int out_size)
{
    const float* hidden    = (const float*)d_in[0];
    const float* past_k    = (const float*)d_in[1];
    const float* past_v    = (const float*)d_in[2];
    const int*   past_lens = (const int*)  d_in[3];
    const float* Wq = (const float*)d_in[4];  const float* bq = (const float*)d_in[5];
    const float* Wk = (const float*)d_in[6];  const float* bk = (const float*)d_in[7];
    const float* Wv = (const float*)d_in[8];  const float* bv = (const float*)d_in[9];
    const float* Wo = (const float*)d_in[10]; const float* bo = (const float*)d_in[11];
    const float* W1 = (const float*)d_in[12]; const float* b1 = (const float*)d_in[13];
    const float* W2 = (const float*)d_in[14]; const float* b2 = (const float*)d_in[15];
    float* out = (float*)d_out;

    float *qkv, *sc, *rp, *at, *h1r, *act, *hr, *wqkv, *bqkv, *wo, *w1, *w2;
    cudaGetSymbolAddress((void**)&qkv,  g_qkv);
    cudaGetSymbolAddress((void**)&sc,   g_sc);
    cudaGetSymbolAddress((void**)&rp,   g_rp);
    cudaGetSymbolAddress((void**)&at,   g_at);
    cudaGetSymbolAddress((void**)&h1r,  g_h1r);
    cudaGetSymbolAddress((void**)&act,  g_act);
    cudaGetSymbolAddress((void**)&hr,   g_hr);
    cudaGetSymbolAddress((void**)&wqkv, g_wqkv);
    cudaGetSymbolAddress((void**)&bqkv, g_bqkv);
    cudaGetSymbolAddress((void**)&wo,   g_wo);
    cudaGetSymbolAddress((void**)&w1,   g_w1);
    cudaGetSymbolAddress((void**)&w2,   g_w2);

    cudaFuncSetAttribute(gemm_tc<true,  E_BIAS,      true >, cudaFuncAttributeMaxDynamicSharedMemorySize, SMEM_GEMM);
    cudaFuncSetAttribute(gemm_tc<false, E_RES_HID,   false>, cudaFuncAttributeMaxDynamicSharedMemorySize, SMEM_GEMM);
    cudaFuncSetAttribute(gemm_tc<false, E_GELU,      true >, cudaFuncAttributeMaxDynamicSharedMemorySize, SMEM_GEMM);
    cudaFuncSetAttribute(gemm_tc<false, E_RES_TRANS, false>, cudaFuncAttributeMaxDynamicSharedMemorySize, SMEM_GEMM);
    cudaFuncSetAttribute(scores_tc, cudaFuncAttributeMaxDynamicSharedMemorySize, SMEM_SCORES);
    cudaFuncSetAttribute(pv_tc,     cudaFuncAttributeMaxDynamicSharedMemorySize, SMEM_GEMM);

    prep_kernel<<<(F4_TOTAL + 255) / 256, 256>>>(hidden, Wq, Wk, Wv, Wo, W1, W2, bq, bk, bv);

    dim3 blk(NT);

    gemm_tc<true, E_BIAS, true><<<dim3(QKVN / BN, Mm / BM), blk, SMEM_GEMM>>>(
        hr, wqkv, bqkv, nullptr, qkv, Hh, QKVN, QKVN);

    scores_tc<<<dim3(Tt / BN, S_ / BM, Bb), blk, SMEM_SCORES>>>(qkv, past_k, past_lens, sc, rp);
    pv_tc<<<dim3(Hh / BN, S_ / BM, Bb), blk, SMEM_GEMM>>>(sc, past_v, qkv, at, past_lens, rp);

    // wo + residual -> single ROUNDED h1 buffer (FFN-A and FFN2 residual)
    gemm_tc<false, E_RES_HID, false><<<dim3(Hh / BN, Mm / BM), blk, SMEM_GEMM>>>(
        at, wo, bo, hidden, h1r, Hh, Hh, Hh);

    gemm_tc<false, E_GELU, true><<<dim3(Ff / BN, Mm / BM), blk, SMEM_GEMM>>>(
        h1r, w1, b1, nullptr, act, Hh, Ff, Ff);
    gemm_tc<false, E_RES_TRANS, false><<<dim3(Hh / BN, Mm / BM), blk, SMEM_GEMM>>>(
        act, w2, b2, h1r, out, Ff, Hh, Hh);
}